// round 2
// baseline (speedup 1.0000x reference)
#include <cuda_runtime.h>

#define BATCH 4
#define C 256
#define H 256
#define W 256
#define S 8
#define HP 32
#define WP 32
#define N 1024     // HP*WP tokens
#define KC 32      // key channels

// ---------------- device scratch (no allocs allowed) ----------------
__device__ float g_xf[BATCH * C * N];        // pooled features  [b][c][n]   4 MB
__device__ float g_q[BATCH * KC * N];        // q                [b][k][n]
__device__ float g_k[BATCH * KC * N];        // k                [b][k][n]
__device__ float g_v[BATCH * C * N];         // v                [b][c][n]   4 MB
__device__ float g_attn[BATCH * N * N];      // softmax probs    [b][n][m]  16 MB
__device__ float g_out[BATCH * C * N];       // attn output      [b][c][n]   4 MB

// ---------------- kernel 1: 8x8 avg pool ----------------
// one thread per (b,c,hp,wp) output; warp covers a full wp row -> coalesced
__global__ void avgpool_kernel(const float* __restrict__ f) {
    int idx = blockIdx.x * blockDim.x + threadIdx.x;   // over BATCH*C*N
    int n  = idx & (N - 1);
    int bc = idx >> 10;
    int wp = n & (WP - 1);
    int hp = n >> 5;
    const float* src = f + ((size_t)bc * H + (size_t)hp * S) * W + (size_t)wp * S;
    float s = 0.f;
#pragma unroll
    for (int r = 0; r < S; r++) {
        float4 a = *(const float4*)(src + (size_t)r * W);
        float4 b = *(const float4*)(src + (size_t)r * W + 4);
        s += a.x + a.y + a.z + a.w + b.x + b.y + b.z + b.w;
    }
    g_xf[idx] = s * (1.f / 64.f);
}

// ---------------- kernel 2: q/k/v 1x1 convs ----------------
// grid: (n_tiles=4, row_groups=20, batch=4), block 256
// each thread owns one token column n and 16 output rows (register blocked)
__global__ void qkv_kernel(const float* __restrict__ qw, const float* __restrict__ qb,
                           const float* __restrict__ kw, const float* __restrict__ kb,
                           const float* __restrict__ vw, const float* __restrict__ vb) {
    __shared__ float wsh[16][C];
    __shared__ float bsh[16];
    int b = blockIdx.z;
    int g = blockIdx.y;
    int n = blockIdx.x * 256 + threadIdx.x;

    const float* wsrc;
    const float* bsrc;
    float* dst;
    int r0;
    if (g < 2)      { wsrc = qw; bsrc = qb; dst = g_q + (size_t)b * KC * N; r0 = g * 16; }
    else if (g < 4) { wsrc = kw; bsrc = kb; dst = g_k + (size_t)b * KC * N; r0 = (g - 2) * 16; }
    else            { wsrc = vw; bsrc = vb; dst = g_v + (size_t)b * C * N;  r0 = (g - 4) * 16; }

    for (int i = threadIdx.x; i < 16 * C; i += 256)
        wsh[i >> 8][i & (C - 1)] = wsrc[(size_t)r0 * C + i];
    if (threadIdx.x < 16) bsh[threadIdx.x] = bsrc[r0 + threadIdx.x];
    __syncthreads();

    const float* xf = g_xf + (size_t)b * C * N + n;
    float acc[16];
#pragma unroll
    for (int r = 0; r < 16; r++) acc[r] = 0.f;

#pragma unroll 4
    for (int c = 0; c < C; c++) {
        float x = xf[(size_t)c * N];
#pragma unroll
        for (int r = 0; r < 16; r++) acc[r] = fmaf(wsh[r][c], x, acc[r]);
    }
#pragma unroll
    for (int r = 0; r < 16; r++)
        dst[(size_t)(r0 + r) * N + n] = acc[r] + bsh[r];
}

// ---------------- kernel 3: energy + softmax ----------------
#define QT 8   // query rows per block
__global__ void attn_prob_kernel() {
    int b  = blockIdx.y;
    int n0 = blockIdx.x * QT;
    int tid  = threadIdx.x;
    int lane = tid & 31, wid = tid >> 5;

    __shared__ float qsh[QT][KC];
    __shared__ float red_m[QT][8];
    __shared__ float red_s[QT][8];

    // load q tile: QT*KC = 256 values
    {
        int r = tid >> 5, k = tid & 31;
        qsh[r][k] = g_q[((size_t)b * KC + k) * N + (n0 + r)];
    }
    __syncthreads();

    float e[QT][4];
#pragma unroll
    for (int r = 0; r < QT; r++)
#pragma unroll
        for (int j = 0; j < 4; j++) e[r][j] = 0.f;

    const float* Kp = g_k + (size_t)b * KC * N;
#pragma unroll 4
    for (int k = 0; k < KC; k++) {
        float kv0 = Kp[(size_t)k * N + tid];
        float kv1 = Kp[(size_t)k * N + tid + 256];
        float kv2 = Kp[(size_t)k * N + tid + 512];
        float kv3 = Kp[(size_t)k * N + tid + 768];
#pragma unroll
        for (int r = 0; r < QT; r++) {
            float qv = qsh[r][k];
            e[r][0] = fmaf(qv, kv0, e[r][0]);
            e[r][1] = fmaf(qv, kv1, e[r][1]);
            e[r][2] = fmaf(qv, kv2, e[r][2]);
            e[r][3] = fmaf(qv, kv3, e[r][3]);
        }
    }

    const float scale = 0.17677669529663687f;   // 32^-0.5
    // phase 1: row maxima
#pragma unroll
    for (int r = 0; r < QT; r++) {
#pragma unroll
        for (int j = 0; j < 4; j++) e[r][j] *= scale;
        float lm = fmaxf(fmaxf(e[r][0], e[r][1]), fmaxf(e[r][2], e[r][3]));
#pragma unroll
        for (int o = 16; o > 0; o >>= 1) lm = fmaxf(lm, __shfl_xor_sync(0xFFFFFFFFu, lm, o));
        if (lane == 0) red_m[r][wid] = lm;
    }
    __syncthreads();

    // phase 2: exp + row sums
#pragma unroll
    for (int r = 0; r < QT; r++) {
        float m2 = red_m[r][0];
#pragma unroll
        for (int w = 1; w < 8; w++) m2 = fmaxf(m2, red_m[r][w]);
        float ls = 0.f;
#pragma unroll
        for (int j = 0; j < 4; j++) { e[r][j] = __expf(e[r][j] - m2); ls += e[r][j]; }
#pragma unroll
        for (int o = 16; o > 0; o >>= 1) ls += __shfl_xor_sync(0xFFFFFFFFu, ls, o);
        if (lane == 0) red_s[r][wid] = ls;
    }
    __syncthreads();

    // phase 3: normalize + store
    float* P = g_attn + (size_t)b * N * N;
#pragma unroll
    for (int r = 0; r < QT; r++) {
        float s2 = red_s[r][0];
#pragma unroll
        for (int w = 1; w < 8; w++) s2 += red_s[r][w];
        float inv = 1.f / s2;
#pragma unroll
        for (int j = 0; j < 4; j++)
            P[(size_t)(n0 + r) * N + tid + j * 256] = e[r][j] * inv;
    }
}

// ---------------- kernel 4: out = v @ attn^T (tiled fp32 GEMM) ----------------
// out[b][c][n] = sum_m v[b][c][m] * attn[b][n][m]
// block tile: 64(c) x 64(n), k-tile 16(m), 256 threads, 4x4 micro-tile
#define BM 64
#define BN 64
#define BK 16
#define SPAD 68   // row stride (floats): mult of 4 -> 16B aligned rows, bank-skewed
__global__ void out_gemm_kernel() {
    int b  = blockIdx.z;
    int c0 = blockIdx.y * BM;
    int n0 = blockIdx.x * BN;
    __shared__ __align__(16) float As[BK][SPAD];  // As[m][c]
    __shared__ __align__(16) float Bs[BK][SPAD];  // Bs[m][n]

    int tid = threadIdx.x;
    int tx = tid & 15, ty = tid >> 4;
    const float* V = g_v    + (size_t)b * C * N;
    const float* P = g_attn + (size_t)b * N * N;

    float acc[4][4];
#pragma unroll
    for (int i = 0; i < 4; i++)
#pragma unroll
        for (int j = 0; j < 4; j++) acc[i][j] = 0.f;

    int mg  = tid & 3;    // float4 index within m-tile
    int row = tid >> 2;   // 0..63

    for (int m0 = 0; m0 < N; m0 += BK) {
        float4 av = *(const float4*)(V + (size_t)(c0 + row) * N + m0 + mg * 4);
        float4 bv = *(const float4*)(P + (size_t)(n0 + row) * N + m0 + mg * 4);
        __syncthreads();
        As[mg * 4 + 0][row] = av.x; As[mg * 4 + 1][row] = av.y;
        As[mg * 4 + 2][row] = av.z; As[mg * 4 + 3][row] = av.w;
        Bs[mg * 4 + 0][row] = bv.x; Bs[mg * 4 + 1][row] = bv.y;
        Bs[mg * 4 + 2][row] = bv.z; Bs[mg * 4 + 3][row] = bv.w;
        __syncthreads();
#pragma unroll
        for (int kk = 0; kk < BK; kk++) {
            float4 a  = *(const float4*)&As[kk][ty * 4];
            float4 bb = *(const float4*)&Bs[kk][tx * 4];
            acc[0][0] = fmaf(a.x, bb.x, acc[0][0]);
            acc[0][1] = fmaf(a.x, bb.y, acc[0][1]);
            acc[0][2] = fmaf(a.x, bb.z, acc[0][2]);
            acc[0][3] = fmaf(a.x, bb.w, acc[0][3]);
            acc[1][0] = fmaf(a.y, bb.x, acc[1][0]);
            acc[1][1] = fmaf(a.y, bb.y, acc[1][1]);
            acc[1][2] = fmaf(a.y, bb.z, acc[1][2]);
            acc[1][3] = fmaf(a.y, bb.w, acc[1][3]);
            acc[2][0] = fmaf(a.z, bb.x, acc[2][0]);
            acc[2][1] = fmaf(a.z, bb.y, acc[2][1]);
            acc[2][2] = fmaf(a.z, bb.z, acc[2][2]);
            acc[2][3] = fmaf(a.z, bb.w, acc[2][3]);
            acc[3][0] = fmaf(a.w, bb.x, acc[3][0]);
            acc[3][1] = fmaf(a.w, bb.y, acc[3][1]);
            acc[3][2] = fmaf(a.w, bb.z, acc[3][2]);
            acc[3][3] = fmaf(a.w, bb.w, acc[3][3]);
        }
    }

    float* O = g_out + (size_t)b * C * N;
#pragma unroll
    for (int i = 0; i < 4; i++) {
        float4 r;
        r.x = acc[i][0]; r.y = acc[i][1]; r.z = acc[i][2]; r.w = acc[i][3];
        *(float4*)(O + (size_t)(c0 + ty * 4 + i) * N + n0 + tx * 4) = r;
    }
}

// ---------------- kernel 5: nearest 8x upsample + residual ----------------
__global__ void upsample_add_kernel(const float* __restrict__ f, float* __restrict__ out) {
    size_t idx = (size_t)blockIdx.x * blockDim.x + threadIdx.x;  // over B*C*H*W/4
    int w4 = (int)(idx & 63);            // W/4 = 64
    int h  = (int)((idx >> 6) & 255);
    size_t bc = idx >> 14;
    int hp = h >> 3;
    int wp = w4 >> 1;                    // (w4*4)/8
    float s = g_out[bc * N + (size_t)hp * WP + wp];
    float4 a = ((const float4*)f)[idx];
    a.x += s; a.y += s; a.z += s; a.w += s;
    ((float4*)out)[idx] = a;
}

// ---------------- launch ----------------
extern "C" void kernel_launch(void* const* d_in, const int* in_sizes, int n_in,
                              void* d_out, int out_size) {
    const float* f  = (const float*)d_in[0];
    const float* qw = (const float*)d_in[1];
    const float* qb = (const float*)d_in[2];
    const float* kw = (const float*)d_in[3];
    const float* kb = (const float*)d_in[4];
    const float* vw = (const float*)d_in[5];
    const float* vb = (const float*)d_in[6];
    float* out = (float*)d_out;

    avgpool_kernel<<<(BATCH * C * N) / 256, 256>>>(f);
    qkv_kernel<<<dim3(4, 20, BATCH), 256>>>(qw, qb, kw, kb, vw, vb);
    attn_prob_kernel<<<dim3(N / QT, BATCH), 256>>>();
    out_gemm_kernel<<<dim3(N / BN, C / BM, BATCH), 256>>>();
    upsample_add_kernel<<<(BATCH * C * H * (W / 4)) / 256, 256>>>(f, out);
}